// round 17
// baseline (speedup 1.0000x reference)
#include <cuda_runtime.h>
#include <cstdint>

// Problem constants
#define NB      2
#define N_SRC   131072
#define N_DST   131072
#define E_CNT   524288
#define FDIM    64
#define F4      (FDIM / 4)     // 16 float4 per feature row
#define EPS_F   1e-8f

#define D_BLK    64            // destinations per gather block
#define BKT      32            // bucket slots per dst (P(overflow) ~ 1e-14)

// ---------------- scratch (__device__ globals; zero-initialized) -------------
// Invariant: every kernel_launch leaves g_cur zeroed (gather resets it), so
// graph replays see identical starting state. Bucket slots beyond the live
// count are stale but never *used* (arithmetically masked in the gather).
__device__ int   g_cur[N_DST];                // per-dst bucket cursor / count
__device__ int2  g_pair[(size_t)N_DST * BKT]; // (src byte-offset, w-bits)

// ---------------------------------------------------------------------------
// K1: bucket fill. One pass over edges; per-dst slot via atomic cursor.
// pair.x is pre-scaled to a byte offset (src * 256).
// ---------------------------------------------------------------------------
__global__ void fill_kernel(const int* __restrict__ src,
                            const int* __restrict__ dst,
                            const float* __restrict__ w) {
    int e = blockIdx.x * blockDim.x + threadIdx.x;
    if (e >= E_CNT) return;
    int d = dst[e] & (N_DST - 1);
    int s = src[e] & (N_SRC - 1);
    int pos = atomicAdd(&g_cur[d], 1);
    if (pos < BKT) {
        g_pair[((size_t)d << 5) + pos] = make_int2(s << 8, __float_as_int(w[e]));
    }
}

// ---------------------------------------------------------------------------
// K2: gather. Block = 256 threads, owns D_BLK=64 contiguous dsts.
//   Phase A: read 64 counts (g_cur), clamp to BKT, reset g_cur for replay.
//   Phase B: LIVE-PREFIX staging — each warp stages only the live slots of
//            its 8 buckets (8 independent predicated LDG rounds, ~1 sector
//            per bucket) instead of bulk-copying all 16 KB (R16 wasted
//            ~30 MB of DRAM on stale slots).
//   Phase C: warp per dst x 8. Branchless 4-wide inner loop: unconditional
//            pair LDS (stays inside the 32-slot bucket: bb<=28), arithmetic
//            masks zero the weight AND offset for tail/unstaged slots.
// __launch_bounds__(256,8): regs<=32 -> up to 8 blocks (2048 thr)/SM.
// ---------------------------------------------------------------------------
__global__ void __launch_bounds__(256, 8)
gather_kernel(const float4* __restrict__ x4, float4* __restrict__ out4) {
    __shared__ int  sh_cnt[D_BLK];
    __shared__ int2 sh_pair[D_BLK * BKT];   // 2048 pairs = 16 KB

    int tid = threadIdx.x;
    int d0  = blockIdx.x * D_BLK;

    // Phase A: counts + replay reset
    if (tid < D_BLK) {
        int c = g_cur[d0 + tid];
        sh_cnt[tid] = c > BKT ? BKT : c;
        g_cur[d0 + tid] = 0;
    }
    __syncthreads();

    int wid  = tid >> 5;
    int lane = tid & 31;

    // Phase B: live-prefix staging, 8 buckets per warp, independent rounds
    {
        const int2* gpp = g_pair + ((size_t)d0 << 5);
#pragma unroll
        for (int k = 0; k < 8; k++) {
            int dl = wid * 8 + k;
            int c  = sh_cnt[dl];
            if (lane < c) {
                sh_pair[(dl << 5) + lane] = gpp[(dl << 5) + lane];
            }
        }
    }
    __syncthreads();

    // Phase C: warp per dst, 8 dsts per warp
    int b  = lane >> 4;
    int fi = lane & 15;
    const char* xb = (const char*)(x4 + (size_t)b * N_SRC * F4 + fi);

#pragma unroll 1
    for (int k = 0; k < 8; k++) {
        int dl = wid * 8 + k;
        int n  = sh_cnt[dl];
        const int2* pp = sh_pair + (dl << 5);

        float4 acc = make_float4(0.f, 0.f, 0.f, 0.f);
        float  sumw = 0.f;

#pragma unroll 1
        for (int bb = 0; bb < n; bb += 4) {
            // Unconditional pair loads (never cross the 32-slot bucket)
            int2 p0 = pp[bb + 0];
            int2 p1 = pp[bb + 1];
            int2 p2 = pp[bb + 2];
            int2 p3 = pp[bb + 3];
            // Arithmetic tail masks: -1 inside segment, 0 past end
            int m1 = -(int)(bb + 1 < n);
            int m2 = -(int)(bb + 2 < n);
            int m3 = -(int)(bb + 3 < n);
            float w0 = __int_as_float(p0.y);
            float w1 = __int_as_float(p1.y & m1);
            float w2 = __int_as_float(p2.y & m2);
            float w3 = __int_as_float(p3.y & m3);
            float4 v0 = *(const float4*)(xb + (unsigned)p0.x);
            float4 v1 = *(const float4*)(xb + (unsigned)(p1.x & m1));
            float4 v2 = *(const float4*)(xb + (unsigned)(p2.x & m2));
            float4 v3 = *(const float4*)(xb + (unsigned)(p3.x & m3));
            acc.x += w0 * v0.x; acc.y += w0 * v0.y;
            acc.z += w0 * v0.z; acc.w += w0 * v0.w;
            acc.x += w1 * v1.x; acc.y += w1 * v1.y;
            acc.z += w1 * v1.z; acc.w += w1 * v1.w;
            acc.x += w2 * v2.x; acc.y += w2 * v2.y;
            acc.z += w2 * v2.z; acc.w += w2 * v2.w;
            acc.x += w3 * v3.x; acc.y += w3 * v3.y;
            acc.z += w3 * v3.z; acc.w += w3 * v3.w;
            sumw += w0 + w1 + w2 + w3;
        }

        float inv = (n > 0) ? (1.0f / (sumw + EPS_F)) : 0.0f;
        float4 o = make_float4(acc.x * inv, acc.y * inv, acc.z * inv, acc.w * inv);
        out4[(size_t)b * N_DST * F4 + (size_t)(d0 + dl) * F4 + fi] = o;
    }
}

// ---------------------------------------------------------------------------
// Launch. Inputs identified by element count:
//   x: 16,777,216 f32   edge_index: 1,048,576 i32   weights: 524,288 f32
// edge_index is [2, E]: first E = src, next E = dst. Output f32 (B,N_DST,F).
// ---------------------------------------------------------------------------
extern "C" void kernel_launch(void* const* d_in, const int* in_sizes, int n_in,
                              void* d_out, int out_size) {
    const float* x   = nullptr;
    const int*   ei  = nullptr;
    const float* wts = nullptr;

    for (int i = 0; i < n_in; i++) {
        if (in_sizes[i] == NB * N_SRC * FDIM)      x   = (const float*)d_in[i];
        else if (in_sizes[i] == 2 * E_CNT)         ei  = (const int*)d_in[i];
        else if (in_sizes[i] == E_CNT)             wts = (const float*)d_in[i];
    }
    if (!x)   x   = (const float*)d_in[0];
    if (!ei)  ei  = (const int*)d_in[1];
    if (!wts) wts = (const float*)d_in[2];

    const int* src = ei;
    const int* dst = ei + E_CNT;
    float* out = (float*)d_out;

    fill_kernel<<<(E_CNT + 255) / 256, 256>>>(src, dst, wts);
    gather_kernel<<<N_DST / D_BLK, 256>>>((const float4*)x, (float4*)out);
}